// round 8
// baseline (speedup 1.0000x reference)
#include <cuda_runtime.h>
#include <math.h>

#define NBINS    8192
#define K_MAX    16384
#define N_MAX    1048576
#define EPSF     1e-8f
#define LOG_BOUND -120.0f
#define MAIN_BLOCKS 1184   /* 148 SMs * 8 resident CTAs */

// ---------------- device scratch (no allocations allowed) ----------------
__device__ unsigned int g_partial_max[1024];
__device__ float g_m;            // softmax max
__device__ float g_Z;            // softmax denominator
__device__ float g_sum_alloc;    // sum of allocation weighting
__device__ int   g_count;        // number of selected (small-usage) elements
__device__ int   g_thresh_bin;   // histogram threshold bin
__device__ float g_key_norm;
__device__ int   g_hist[NBINS];
__device__ float g_s[N_MAX];     // cosine*beta scores
__device__ float g_buf_u[K_MAX];
__device__ float g_buf_lu[K_MAX];
__device__ float g_buf_a[K_MAX];
__device__ int   g_buf_idx[K_MAX];

// orderable-uint encoding for float atomic max (handles negatives)
__device__ __forceinline__ unsigned int enc_f(float f) {
    unsigned int u = __float_as_uint(f);
    return (u & 0x80000000u) ? ~u : (u | 0x80000000u);
}
__device__ __forceinline__ float dec_f(unsigned int u) {
    return (u & 0x80000000u) ? __uint_as_float(u & 0x7FFFFFFFu)
                             : __uint_as_float(~u);
}

// ---- kernel A (idx 0): key norm + scalars ----
__global__ void k_init(const float* __restrict__ key) {
    if (blockIdx.x == 0) {
        __shared__ float sh[64];
        if (threadIdx.x < 64) {
            float k = key[threadIdx.x];
            sh[threadIdx.x] = k * k;
        }
        __syncthreads();
        if (threadIdx.x == 0) {
            float t = 0.0f;
            for (int j = 0; j < 64; j++) t += sh[j];
            g_key_norm = sqrtf(t);
            g_Z = 0.0f;
            g_sum_alloc = 0.0f;
            g_count = 0;
            g_thresh_bin = NBINS - 1;
        }
    }
}

// ---- kernel B (idx 1): clear partial-max array ----
__global__ void k_zero_a() {
    int i = blockIdx.x * blockDim.x + threadIdx.x;
    if (i < 1024) g_partial_max[i] = 0u;
}

// ---- kernel C (idx 2): clear histogram ----
__global__ void k_zero_b() {
    int i = blockIdx.x * blockDim.x + threadIdx.x;
    if (i < NBINS) g_hist[i] = 0;
}

// ---- kernel 1 (idx 3): PERSISTENT main pass (grid-stride, 4 rows/warp/iter)
__global__ void k_main(const float4* __restrict__ mem4,
                       const float4* __restrict__ key4,
                       const float* __restrict__ beta_p,
                       const float* __restrict__ fg,
                       const float* __restrict__ rw,
                       const float* __restrict__ pu,
                       const float* __restrict__ pw,
                       float* __restrict__ out_usage,
                       int N) {
    __shared__ unsigned int smax[8];
    int lane = threadIdx.x & 31;
    int wid  = threadIdx.x >> 5;

    int sub = lane >> 4;           // 0/1: which row of each pair
    int l16 = lane & 15;
    int l8  = lane & 7;

    float4 k4  = key4[l16];
    float beta = beta_p[0];
    float kn   = fmaxf(g_key_norm, EPSF);
    float f    = (l16 < 8) ? fg[l8] : 0.0f;

    int nTasks   = (N + 3) >> 2;                        // 4 rows per task
    int warpsAll = (gridDim.x * blockDim.x) >> 5;
    int gw0      = (blockIdx.x * blockDim.x + threadIdx.x) >> 5;

    unsigned int encAcc = 0u;

    for (int t = gw0; t < nTasks; t += warpsAll) {
        int rowA = t * 4 + sub;
        int rowB = rowA + 2;
        bool actA = rowA < N;
        bool actB = rowB < N;

        float4 ma = make_float4(0.f, 0.f, 0.f, 0.f);
        float4 mb = make_float4(0.f, 0.f, 0.f, 0.f);
        if (actA) ma = mem4[(size_t)rowA * 16 + l16];
        if (actB) mb = mem4[(size_t)rowB * 16 + l16];

        float dotA = ma.x * k4.x + ma.y * k4.y + ma.z * k4.z + ma.w * k4.w;
        float sqA  = ma.x * ma.x + ma.y * ma.y + ma.z * ma.z + ma.w * ma.w;
        float dotB = mb.x * k4.x + mb.y * k4.y + mb.z * k4.z + mb.w * k4.w;
        float sqB  = mb.x * mb.x + mb.y * mb.y + mb.z * mb.z + mb.w * mb.w;
#pragma unroll
        for (int o = 8; o; o >>= 1) {
            dotA += __shfl_xor_sync(0xFFFFFFFFu, dotA, o);
            sqA  += __shfl_xor_sync(0xFFFFFFFFu, sqA, o);
            dotB += __shfl_xor_sync(0xFFFFFFFFu, dotB, o);
            sqB  += __shfl_xor_sync(0xFFFFFFFFu, sqB, o);
        }

        float pA = 1.0f, pB = 1.0f;
        if (l16 < 8) {
            if (actA) pA = 1.0f - rw[rowA * 8 + l8] * f;
            if (actB) pB = 1.0f - rw[rowB * 8 + l8] * f;
        }
#pragma unroll
        for (int o = 4; o; o >>= 1) {
            pA *= __shfl_xor_sync(0xFFFFFFFFu, pA, o);
            pB *= __shfl_xor_sync(0xFFFFFFFFu, pB, o);
        }

        if (l16 == 0) {
            if (actA) {
                float denom = fmaxf(sqrtf(sqA), EPSF) * kn;
                float s = (dotA / denom) * beta;
                g_s[rowA] = s;
                float a = pu[rowA], b = pw[rowA];
                float u_ = (a + b - a * b) * pA;
                out_usage[rowA] = u_;
                int bin = max(0, min((int)(u_ * (float)NBINS), NBINS - 1));
                atomicAdd(&g_hist[bin], 1);
                encAcc = max(encAcc, enc_f(s));
            }
            if (actB) {
                float denom = fmaxf(sqrtf(sqB), EPSF) * kn;
                float s = (dotB / denom) * beta;
                g_s[rowB] = s;
                float a = pu[rowB], b = pw[rowB];
                float u_ = (a + b - a * b) * pB;
                out_usage[rowB] = u_;
                int bin = max(0, min((int)(u_ * (float)NBINS), NBINS - 1));
                atomicAdd(&g_hist[bin], 1);
                encAcc = max(encAcc, enc_f(s));
            }
        }
    }

    // warp max, then block max, one atomic per block at the very end
#pragma unroll
    for (int o = 16; o; o >>= 1)
        encAcc = max(encAcc, __shfl_xor_sync(0xFFFFFFFFu, encAcc, o));
    if (lane == 0) smax[wid] = encAcc;
    __syncthreads();
    if (threadIdx.x == 0) {
        unsigned int mx = 0u;
#pragma unroll
        for (int j = 0; j < 8; j++) mx = max(mx, smax[j]);
        atomicMax(&g_partial_max[blockIdx.x & 1023], mx);
    }
}

// ---------------- kernel 2: global max + threshold bin ----------------
__global__ void k_thresh() {
    __shared__ unsigned int sm[1024];
    __shared__ float spre[1024];
    int t = threadIdx.x;

    sm[t] = g_partial_max[t];
    __syncthreads();
    for (int o = 512; o; o >>= 1) {
        if (t < o) sm[t] = max(sm[t], sm[t + o]);
        __syncthreads();
    }
    if (t == 0) g_m = dec_f(sm[0]);

    const float inv = 1.0f / (float)NBINS;
    const int BPT = NBINS / 1024;       // 8
    int base = t * BPT;
    int cnt[BPT];
    float local = 0.0f;
#pragma unroll
    for (int b = 0; b < BPT; b++) {
        cnt[b] = g_hist[base + b];
        if (cnt[b]) local += (float)cnt[b] * __logf((float)(base + b + 1) * inv);
    }
    spre[t] = local;
    __syncthreads();
    for (int o = 1; o < 1024; o <<= 1) {
        float v = (t >= o) ? spre[t - o] : 0.0f;
        __syncthreads();
        spre[t] += v;
        __syncthreads();
    }
    float prefix = (t == 0) ? 0.0f : spre[t - 1];
    if (prefix <= LOG_BOUND) {
        atomicMin(&g_thresh_bin, base);
    } else {
        float run = prefix;
#pragma unroll
        for (int b = 0; b < BPT; b++) {
            if (cnt[b]) run += (float)cnt[b] * __logf((float)(base + b + 1) * inv);
            if (run <= LOG_BOUND) {
                atomicMin(&g_thresh_bin, base + b);
                break;
            }
        }
    }
}

// ---------------- kernel 3: softmax denominator + gather small-usage set ----
__global__ void k_gather(const float4* __restrict__ usage4, int N4) {
    __shared__ float sh[8];
    int i = blockIdx.x * blockDim.x + threadIdx.x;
    int lane = threadIdx.x & 31;
    int wid  = threadIdx.x >> 5;
    float e = 0.0f;
    float m = g_m;
    int tb = g_thresh_bin;
    if (i < N4) {
        const float4 s4 = reinterpret_cast<const float4*>(g_s)[i];
        float4 u4 = usage4[i];
        e = expf(s4.x - m) + expf(s4.y - m) + expf(s4.z - m) + expf(s4.w - m);
        float uu[4] = {u4.x, u4.y, u4.z, u4.w};
#pragma unroll
        for (int c = 0; c < 4; c++) {
            int bin = (int)(uu[c] * (float)NBINS);
            bin = max(0, min(bin, NBINS - 1));
            if (bin <= tb) {
                int p = atomicAdd(&g_count, 1);
                if (p < K_MAX) {
                    g_buf_u[p] = uu[c];
                    g_buf_lu[p] = logf(uu[c]);
                    g_buf_idx[p] = i * 4 + c;
                }
            }
        }
    }
#pragma unroll
    for (int o = 16; o; o >>= 1) e += __shfl_xor_sync(0xFFFFFFFFu, e, o);
    if (lane == 0) sh[wid] = e;
    __syncthreads();
    if (threadIdx.x == 0) {
        float t = 0.0f;
#pragma unroll
        for (int j = 0; j < 8; j++) t += sh[j];
        atomicAdd(&g_Z, t);
    }
}

// ---------------- kernel 4: allocation for selected head (warp / element) ----
__global__ void k_alloc() {
    int C = min(g_count, K_MAX);
    int w = (blockIdx.x * blockDim.x + threadIdx.x) >> 5;
    int lane = threadIdx.x & 31;
    if (w >= C) return;
    float ui = g_buf_u[w];
    int ii = g_buf_idx[w];
    float S = 0.0f;
    for (int j = lane; j < C; j += 32) {
        float uj = g_buf_u[j];
        bool before = (uj < ui) || (uj == ui && g_buf_idx[j] < ii);
        if (before) S += g_buf_lu[j];
    }
#pragma unroll
    for (int o = 16; o; o >>= 1) S += __shfl_xor_sync(0xFFFFFFFFu, S, o);
    if (lane == 0) {
        float a = (1.0f - ui) * expf(S);
        g_buf_a[w] = a;
        atomicAdd(&g_sum_alloc, a);
    }
}

// ---------------- kernel 5: finalize content part of ww + precedence --------
__global__ void k_final(const float4* __restrict__ prec4,
                        const float* __restrict__ ag_p,
                        const float* __restrict__ wg_p,
                        float* __restrict__ out, int N, int N4) {
    int i = blockIdx.x * blockDim.x + threadIdx.x;
    if (i >= N4) return;
    float invZ = 1.0f / g_Z;
    float m = g_m;
    float ag = ag_p[0];
    float wg = wg_p[0];
    float cw = wg * (1.0f - ag);
    float sum_ww = wg * (ag * g_sum_alloc + (1.0f - ag));
    float oms = 1.0f - sum_ww;

    float4 s4 = reinterpret_cast<const float4*>(g_s)[i];
    float4 p4 = prec4[i];
    float4 ww, np;
    ww.x = cw * expf(s4.x - m) * invZ;
    ww.y = cw * expf(s4.y - m) * invZ;
    ww.z = cw * expf(s4.z - m) * invZ;
    ww.w = cw * expf(s4.w - m) * invZ;
    np.x = oms * p4.x + ww.x;
    np.y = oms * p4.y + ww.y;
    np.z = oms * p4.z + ww.z;
    np.w = oms * p4.w + ww.w;
    reinterpret_cast<float4*>(out)[i] = ww;
    reinterpret_cast<float4*>(out + 2 * N)[i] = np;
}

// ---------------- kernel 6: scatter-add allocation contributions ------------
__global__ void k_apply(const float* __restrict__ ag_p,
                        const float* __restrict__ wg_p,
                        float* __restrict__ out, int N) {
    int C = min(g_count, K_MAX);
    int w = blockIdx.x * blockDim.x + threadIdx.x;
    if (w >= C) return;
    float val = wg_p[0] * ag_p[0] * g_buf_a[w];
    int ii = g_buf_idx[w];
    out[ii] += val;          // indices unique -> no atomics needed
    out[2 * N + ii] += val;
}

// ---------------- launcher ----------------
extern "C" void kernel_launch(void* const* d_in, const int* in_sizes, int n_in,
                              void* d_out, int out_size) {
    const float* mem  = (const float*)d_in[0];
    const float* key  = (const float*)d_in[1];
    const float* beta = (const float*)d_in[2];
    const float* fg   = (const float*)d_in[3];
    const float* rw   = (const float*)d_in[4];
    const float* pu   = (const float*)d_in[5];
    const float* pw   = (const float*)d_in[6];
    const float* ag   = (const float*)d_in[7];
    const float* wg   = (const float*)d_in[8];
    const float* prec = (const float*)d_in[9];

    int N = in_sizes[0] / 64;   // W = 64
    int N4 = N / 4;

    float* out = (float*)d_out;
    float* out_usage = out + N; // outputs: [ww | usage | new_precedence]

    k_init<<<1, 64>>>(key);                 // idx 0
    k_zero_a<<<4, 256>>>();                 // idx 1
    k_zero_b<<<NBINS / 256, 256>>>();       // idx 2
    k_main<<<MAIN_BLOCKS, 256>>>(           // idx 3  (ncu -s 5 lands here)
        (const float4*)mem, (const float4*)key, beta, fg, rw, pu, pw,
        out_usage, N);
    k_thresh<<<1, 1024>>>();
    k_gather<<<(N4 + 255) / 256, 256>>>((const float4*)out_usage, N4);
    k_alloc<<<512, 1024>>>();
    k_final<<<(N4 + 255) / 256, 256>>>((const float4*)prec, ag, wg, out, N, N4);
    k_apply<<<(K_MAX + 255) / 256, 256>>>(ag, wg, out, N);
}

// round 10
// speedup vs baseline: 1.1619x; 1.1619x over previous
#include <cuda_runtime.h>
#include <math.h>

#define NBINS    8192
#define K_MAX    16384
#define N_MAX    1048576
#define EPSF     1e-8f
#define LOG_BOUND -120.0f
#define TILE_ROWS 256
#define MAIN_SMEM (TILE_ROWS * 16 * sizeof(float4))   /* 64 KB */

// ---------------- device scratch (no allocations allowed) ----------------
__device__ unsigned int g_partial_max[1024];
__device__ float g_m;            // softmax max
__device__ float g_Z;            // softmax denominator
__device__ float g_sum_alloc;    // sum of allocation weighting
__device__ int   g_count;        // number of selected (small-usage) elements
__device__ int   g_thresh_bin;   // histogram threshold bin
__device__ float g_key_norm;
__device__ int   g_hist[NBINS];
__device__ float g_s[N_MAX];     // cosine*beta scores
__device__ float g_buf_u[K_MAX];
__device__ float g_buf_lu[K_MAX];
__device__ float g_buf_a[K_MAX];
__device__ int   g_buf_idx[K_MAX];

// orderable-uint encoding for float atomic max (handles negatives)
__device__ __forceinline__ unsigned int enc_f(float f) {
    unsigned int u = __float_as_uint(f);
    return (u & 0x80000000u) ? ~u : (u | 0x80000000u);
}
__device__ __forceinline__ float dec_f(unsigned int u) {
    return (u & 0x80000000u) ? __uint_as_float(u & 0x7FFFFFFFu)
                             : __uint_as_float(~u);
}

// ---- kernel A (idx 0): key norm + scalars ----
__global__ void k_init(const float* __restrict__ key) {
    if (blockIdx.x == 0) {
        __shared__ float sh[64];
        if (threadIdx.x < 64) {
            float k = key[threadIdx.x];
            sh[threadIdx.x] = k * k;
        }
        __syncthreads();
        if (threadIdx.x == 0) {
            float t = 0.0f;
            for (int j = 0; j < 64; j++) t += sh[j];
            g_key_norm = sqrtf(t);
            g_Z = 0.0f;
            g_sum_alloc = 0.0f;
            g_count = 0;
            g_thresh_bin = NBINS - 1;
        }
    }
}

// ---- kernel B (idx 1): clear partial-max array ----
__global__ void k_zero_a() {
    int i = blockIdx.x * blockDim.x + threadIdx.x;
    if (i < 1024) g_partial_max[i] = 0u;
}

// ---- kernel C (idx 2): clear histogram ----
__global__ void k_zero_b() {
    int i = blockIdx.x * blockDim.x + threadIdx.x;
    if (i < NBINS) g_hist[i] = 0;
}

// ---- kernel 1 (idx 3): tile-transpose main pass, thread-per-row compute ---
// smem tile: 256 rows x 16 float4, physical slot = j ^ (row & 15)
//  -> STS.128 and LDS.128 both conflict-free per quarter-warp.
__global__ void k_main(const float4* __restrict__ mem4,
                       const float4* __restrict__ key4,
                       const float* __restrict__ beta_p,
                       const float* __restrict__ fg,
                       const float4* __restrict__ rw4,
                       const float* __restrict__ pu,
                       const float* __restrict__ pw,
                       float* __restrict__ out_usage,
                       int N) {
    extern __shared__ float4 tile[];          // TILE_ROWS*16 float4 (64 KB)
    __shared__ float4 skey[16];
    __shared__ unsigned int smax[8];

    int tid  = threadIdx.x;
    int lane = tid & 31;
    int wid  = tid >> 5;
    int R0   = blockIdx.x * TILE_ROWS;
    int r    = R0 + tid;                      // this thread's row
    bool act = r < N;

    if (tid < 16) skey[tid] = key4[tid];
    if (tid < 8)  smax[tid] = 0u;

    // ---- phase 1: coalesced tile load + swizzled STS; prefetch epilogue data
    // two chunks of 8 LDG.128 to keep per-thread MLP ~8
    const float4* src = mem4 + (size_t)R0 * 16;
    int maxfi = (N - R0) * 16;                // valid float4s in this tile
#pragma unroll
    for (int half = 0; half < 2; half++) {
        float4 v[8];
#pragma unroll
        for (int c = 0; c < 8; c++) {
            int fi = (half * 8 + c) * TILE_ROWS + tid;
            v[c] = (fi < maxfi) ? src[fi] : make_float4(0.f, 0.f, 0.f, 0.f);
        }
#pragma unroll
        for (int c = 0; c < 8; c++) {
            int fi  = (half * 8 + c) * TILE_ROWS + tid;
            int row = fi >> 4;
            int j   = fi & 15;
            tile[row * 16 + (j ^ (row & 15))] = v[c];
        }
    }

    // epilogue operands in flight while we compute from smem
    float4 rwa = make_float4(0.f, 0.f, 0.f, 0.f);
    float4 rwb = make_float4(0.f, 0.f, 0.f, 0.f);
    float a = 0.f, b = 0.f;
    if (act) {
        rwa = rw4[(size_t)r * 2];
        rwb = rw4[(size_t)r * 2 + 1];
        a = pu[r];
        b = pw[r];
    }
    const float4* fgv = reinterpret_cast<const float4*>(fg);
    float4 f0 = fgv[0], f1 = fgv[1];
    float beta = beta_p[0];
    float kn = fmaxf(g_key_norm, EPSF);
    __syncthreads();

    // ---- phase 2: thread-per-row dot + normSq from smem (no shuffles) -----
    float dot = 0.0f, sq = 0.0f;
    {
        const float4* row = tile + tid * 16;
        int rx = tid & 15;
#pragma unroll
        for (int j = 0; j < 16; j++) {
            float4 v = row[j ^ rx];
            float4 k = skey[j];
            dot += v.x * k.x + v.y * k.y + v.z * k.z + v.w * k.w;
            sq  += v.x * v.x + v.y * v.y + v.z * v.z + v.w * v.w;
        }
    }

    // ---- epilogue: fully coalesced, per-thread -----------------------------
    unsigned int enc = 0u;
    if (act) {
        float denom = fmaxf(sqrtf(sq), EPSF) * kn;
        float s = (dot / denom) * beta;
        g_s[r] = s;
        enc = enc_f(s);

        float ret = (1.0f - rwa.x * f0.x) * (1.0f - rwa.y * f0.y)
                  * (1.0f - rwa.z * f0.z) * (1.0f - rwa.w * f0.w)
                  * (1.0f - rwb.x * f1.x) * (1.0f - rwb.y * f1.y)
                  * (1.0f - rwb.z * f1.z) * (1.0f - rwb.w * f1.w);
        float u_ = (a + b - a * b) * ret;
        out_usage[r] = u_;
        int bin = max(0, min((int)(u_ * (float)NBINS), NBINS - 1));
        atomicAdd(&g_hist[bin], 1);
    }

    // block max -> one atomic per block
#pragma unroll
    for (int o = 16; o; o >>= 1)
        enc = max(enc, __shfl_xor_sync(0xFFFFFFFFu, enc, o));
    if (lane == 0) smax[wid] = enc;
    __syncthreads();
    if (tid == 0) {
        unsigned int mx = 0u;
#pragma unroll
        for (int j = 0; j < 8; j++) mx = max(mx, smax[j]);
        atomicMax(&g_partial_max[blockIdx.x & 1023], mx);
    }
}

// ---------------- kernel 2: global max + threshold bin ----------------
__global__ void k_thresh() {
    __shared__ unsigned int sm[1024];
    __shared__ float spre[1024];
    int t = threadIdx.x;

    sm[t] = g_partial_max[t];
    __syncthreads();
    for (int o = 512; o; o >>= 1) {
        if (t < o) sm[t] = max(sm[t], sm[t + o]);
        __syncthreads();
    }
    if (t == 0) g_m = dec_f(sm[0]);

    const float inv = 1.0f / (float)NBINS;
    const int BPT = NBINS / 1024;       // 8
    int base = t * BPT;
    int cnt[BPT];
    float local = 0.0f;
#pragma unroll
    for (int b = 0; b < BPT; b++) {
        cnt[b] = g_hist[base + b];
        if (cnt[b]) local += (float)cnt[b] * __logf((float)(base + b + 1) * inv);
    }
    spre[t] = local;
    __syncthreads();
    for (int o = 1; o < 1024; o <<= 1) {
        float v = (t >= o) ? spre[t - o] : 0.0f;
        __syncthreads();
        spre[t] += v;
        __syncthreads();
    }
    float prefix = (t == 0) ? 0.0f : spre[t - 1];
    if (prefix <= LOG_BOUND) {
        atomicMin(&g_thresh_bin, base);
    } else {
        float run = prefix;
#pragma unroll
        for (int b = 0; b < BPT; b++) {
            if (cnt[b]) run += (float)cnt[b] * __logf((float)(base + b + 1) * inv);
            if (run <= LOG_BOUND) {
                atomicMin(&g_thresh_bin, base + b);
                break;
            }
        }
    }
}

// ---------------- kernel 3: softmax denominator + gather small-usage set ----
__global__ void k_gather(const float4* __restrict__ usage4, int N4) {
    __shared__ float sh[8];
    int i = blockIdx.x * blockDim.x + threadIdx.x;
    int lane = threadIdx.x & 31;
    int wid  = threadIdx.x >> 5;
    float e = 0.0f;
    float m = g_m;
    int tb = g_thresh_bin;
    if (i < N4) {
        const float4 s4 = reinterpret_cast<const float4*>(g_s)[i];
        float4 u4 = usage4[i];
        e = expf(s4.x - m) + expf(s4.y - m) + expf(s4.z - m) + expf(s4.w - m);
        float uu[4] = {u4.x, u4.y, u4.z, u4.w};
#pragma unroll
        for (int c = 0; c < 4; c++) {
            int bin = (int)(uu[c] * (float)NBINS);
            bin = max(0, min(bin, NBINS - 1));
            if (bin <= tb) {
                int p = atomicAdd(&g_count, 1);
                if (p < K_MAX) {
                    g_buf_u[p] = uu[c];
                    g_buf_lu[p] = logf(uu[c]);
                    g_buf_idx[p] = i * 4 + c;
                }
            }
        }
    }
#pragma unroll
    for (int o = 16; o; o >>= 1) e += __shfl_xor_sync(0xFFFFFFFFu, e, o);
    if (lane == 0) sh[wid] = e;
    __syncthreads();
    if (threadIdx.x == 0) {
        float t = 0.0f;
#pragma unroll
        for (int j = 0; j < 8; j++) t += sh[j];
        atomicAdd(&g_Z, t);
    }
}

// ---------------- kernel 4: allocation for selected head (warp / element) ----
__global__ void k_alloc() {
    int C = min(g_count, K_MAX);
    int w = (blockIdx.x * blockDim.x + threadIdx.x) >> 5;
    int lane = threadIdx.x & 31;
    if (w >= C) return;
    float ui = g_buf_u[w];
    int ii = g_buf_idx[w];
    float S = 0.0f;
    for (int j = lane; j < C; j += 32) {
        float uj = g_buf_u[j];
        bool before = (uj < ui) || (uj == ui && g_buf_idx[j] < ii);
        if (before) S += g_buf_lu[j];
    }
#pragma unroll
    for (int o = 16; o; o >>= 1) S += __shfl_xor_sync(0xFFFFFFFFu, S, o);
    if (lane == 0) {
        float a = (1.0f - ui) * expf(S);
        g_buf_a[w] = a;
        atomicAdd(&g_sum_alloc, a);
    }
}

// ---------------- kernel 5: finalize content part of ww + precedence --------
__global__ void k_final(const float4* __restrict__ prec4,
                        const float* __restrict__ ag_p,
                        const float* __restrict__ wg_p,
                        float* __restrict__ out, int N, int N4) {
    int i = blockIdx.x * blockDim.x + threadIdx.x;
    if (i >= N4) return;
    float invZ = 1.0f / g_Z;
    float m = g_m;
    float ag = ag_p[0];
    float wg = wg_p[0];
    float cw = wg * (1.0f - ag);
    float sum_ww = wg * (ag * g_sum_alloc + (1.0f - ag));
    float oms = 1.0f - sum_ww;

    float4 s4 = reinterpret_cast<const float4*>(g_s)[i];
    float4 p4 = prec4[i];
    float4 ww, np;
    ww.x = cw * expf(s4.x - m) * invZ;
    ww.y = cw * expf(s4.y - m) * invZ;
    ww.z = cw * expf(s4.z - m) * invZ;
    ww.w = cw * expf(s4.w - m) * invZ;
    np.x = oms * p4.x + ww.x;
    np.y = oms * p4.y + ww.y;
    np.z = oms * p4.z + ww.z;
    np.w = oms * p4.w + ww.w;
    reinterpret_cast<float4*>(out)[i] = ww;
    reinterpret_cast<float4*>(out + 2 * N)[i] = np;
}

// ---------------- kernel 6: scatter-add allocation contributions ------------
__global__ void k_apply(const float* __restrict__ ag_p,
                        const float* __restrict__ wg_p,
                        float* __restrict__ out, int N) {
    int C = min(g_count, K_MAX);
    int w = blockIdx.x * blockDim.x + threadIdx.x;
    if (w >= C) return;
    float val = wg_p[0] * ag_p[0] * g_buf_a[w];
    int ii = g_buf_idx[w];
    out[ii] += val;          // indices unique -> no atomics needed
    out[2 * N + ii] += val;
}

// ---------------- launcher ----------------
extern "C" void kernel_launch(void* const* d_in, const int* in_sizes, int n_in,
                              void* d_out, int out_size) {
    const float* mem  = (const float*)d_in[0];
    const float* key  = (const float*)d_in[1];
    const float* beta = (const float*)d_in[2];
    const float* fg   = (const float*)d_in[3];
    const float* rw   = (const float*)d_in[4];
    const float* pu   = (const float*)d_in[5];
    const float* pw   = (const float*)d_in[6];
    const float* ag   = (const float*)d_in[7];
    const float* wg   = (const float*)d_in[8];
    const float* prec = (const float*)d_in[9];

    int N = in_sizes[0] / 64;   // W = 64
    int N4 = N / 4;

    float* out = (float*)d_out;
    float* out_usage = out + N; // outputs: [ww | usage | new_precedence]

    static int smem_set = 0;
    if (!smem_set) {
        cudaFuncSetAttribute(k_main, cudaFuncAttributeMaxDynamicSharedMemorySize,
                             (int)MAIN_SMEM);
        smem_set = 1;
    }

    k_init<<<1, 64>>>(key);                 // idx 0
    k_zero_a<<<4, 256>>>();                 // idx 1
    k_zero_b<<<NBINS / 256, 256>>>();       // idx 2
    k_main<<<(N + TILE_ROWS - 1) / TILE_ROWS, 256, MAIN_SMEM>>>(   // idx 3
        (const float4*)mem, (const float4*)key, beta, fg, (const float4*)rw,
        pu, pw, out_usage, N);
    k_thresh<<<1, 1024>>>();
    k_gather<<<(N4 + 255) / 256, 256>>>((const float4*)out_usage, N4);
    k_alloc<<<512, 1024>>>();
    k_final<<<(N4 + 255) / 256, 256>>>((const float4*)prec, ag, wg, out, N, N4);
    k_apply<<<(K_MAX + 255) / 256, 256>>>(ag, wg, out, N);
}

// round 11
// speedup vs baseline: 1.1761x; 1.0123x over previous
#include <cuda_runtime.h>
#include <math.h>

#define NBINS    8192
#define K_MAX    16384
#define N_MAX    1048576
#define EPSF     1e-8f
#define LOG_BOUND -120.0f
#define TILE_ROWS 128
#define MAIN_SMEM (TILE_ROWS * 16 * sizeof(float4))   /* 32 KB */

// ---------------- device scratch (no allocations allowed) ----------------
__device__ unsigned int g_partial_max[1024];
__device__ float g_m;            // softmax max
__device__ float g_Z;            // softmax denominator
__device__ float g_sum_alloc;    // sum of allocation weighting
__device__ int   g_count;        // number of selected (small-usage) elements
__device__ int   g_thresh_bin;   // histogram threshold bin
__device__ float g_key_norm;
__device__ int   g_hist[NBINS];
__device__ float g_s[N_MAX];     // cosine*beta scores
__device__ float g_buf_u[K_MAX];
__device__ float g_buf_lu[K_MAX];
__device__ float g_buf_a[K_MAX];
__device__ int   g_buf_idx[K_MAX];

// orderable-uint encoding for float atomic max (handles negatives)
__device__ __forceinline__ unsigned int enc_f(float f) {
    unsigned int u = __float_as_uint(f);
    return (u & 0x80000000u) ? ~u : (u | 0x80000000u);
}
__device__ __forceinline__ float dec_f(unsigned int u) {
    return (u & 0x80000000u) ? __uint_as_float(u & 0x7FFFFFFFu)
                             : __uint_as_float(~u);
}

// ---- kernel A (idx 0): key norm + scalars ----
__global__ void k_init(const float* __restrict__ key) {
    if (blockIdx.x == 0) {
        __shared__ float sh[64];
        if (threadIdx.x < 64) {
            float k = key[threadIdx.x];
            sh[threadIdx.x] = k * k;
        }
        __syncthreads();
        if (threadIdx.x == 0) {
            float t = 0.0f;
            for (int j = 0; j < 64; j++) t += sh[j];
            g_key_norm = sqrtf(t);
            g_Z = 0.0f;
            g_sum_alloc = 0.0f;
            g_count = 0;
            g_thresh_bin = NBINS - 1;
        }
    }
}

// ---- kernel B (idx 1): clear partial-max array ----
__global__ void k_zero_a() {
    int i = blockIdx.x * blockDim.x + threadIdx.x;
    if (i < 1024) g_partial_max[i] = 0u;
}

// ---- kernel C (idx 2): clear histogram ----
__global__ void k_zero_b() {
    int i = blockIdx.x * blockDim.x + threadIdx.x;
    if (i < NBINS) g_hist[i] = 0;
}

// ---- kernel 1 (idx 3): tile-transpose main pass, thread-per-row compute ---
// block = 256 threads, tile = 128 rows x 16 float4 (32 KB smem).
// physical smem slot = j ^ (row & 15) -> STS.128 and LDS.128 conflict-free.
// threads 0..127 each own one row in phase 2; threads 128..255 idle there
// but carry half the phase-1 loads (fi covers the whole tile).
__global__ void k_main(const float4* __restrict__ mem4,
                       const float4* __restrict__ key4,
                       const float* __restrict__ beta_p,
                       const float* __restrict__ fg,
                       const float4* __restrict__ rw4,
                       const float* __restrict__ pu,
                       const float* __restrict__ pw,
                       float* __restrict__ out_usage,
                       int N) {
    extern __shared__ float4 tile[];          // TILE_ROWS*16 float4 (32 KB)
    __shared__ float4 skey[16];
    __shared__ unsigned int smax[8];

    int tid  = threadIdx.x;
    int lane = tid & 31;
    int wid  = tid >> 5;
    int R0   = blockIdx.x * TILE_ROWS;
    int r    = R0 + tid;                      // row for phase-2 (tid < 128)
    bool act = (tid < TILE_ROWS) && (r < N);

    if (tid < 16) skey[tid] = key4[tid];
    if (tid < 8)  smax[tid] = 0u;

    // ---- phase 1: coalesced tile load + swizzled STS (8 LDG.128 / thread)
    const float4* src = mem4 + (size_t)R0 * 16;
    int maxfi = (N - R0) * 16;                // valid float4s in this tile
    {
        float4 v[8];
#pragma unroll
        for (int c = 0; c < 8; c++) {
            int fi = c * 256 + tid;
            v[c] = (fi < maxfi) ? src[fi] : make_float4(0.f, 0.f, 0.f, 0.f);
        }
#pragma unroll
        for (int c = 0; c < 8; c++) {
            int fi  = c * 256 + tid;
            int row = fi >> 4;
            int j   = fi & 15;
            tile[row * 16 + (j ^ (row & 15))] = v[c];
        }
    }

    // epilogue operands in flight while we compute from smem
    float4 rwa = make_float4(0.f, 0.f, 0.f, 0.f);
    float4 rwb = make_float4(0.f, 0.f, 0.f, 0.f);
    float a = 0.f, b = 0.f;
    if (act) {
        rwa = rw4[(size_t)r * 2];
        rwb = rw4[(size_t)r * 2 + 1];
        a = pu[r];
        b = pw[r];
    }
    const float4* fgv = reinterpret_cast<const float4*>(fg);
    float4 f0 = fgv[0], f1 = fgv[1];
    float beta = beta_p[0];
    float kn = fmaxf(g_key_norm, EPSF);
    __syncthreads();

    // ---- phase 2: thread-per-row dot + normSq from smem (threads 0..127) --
    unsigned int enc = 0u;
    if (act) {
        float dot = 0.0f, sq = 0.0f;
        const float4* row = tile + tid * 16;
        int rx = tid & 15;
#pragma unroll
        for (int j = 0; j < 16; j++) {
            float4 v = row[j ^ rx];
            float4 k = skey[j];
            dot += v.x * k.x + v.y * k.y + v.z * k.z + v.w * k.w;
            sq  += v.x * v.x + v.y * v.y + v.z * v.z + v.w * v.w;
        }

        float denom = fmaxf(sqrtf(sq), EPSF) * kn;
        float s = (dot / denom) * beta;
        g_s[r] = s;
        enc = enc_f(s);

        float ret = (1.0f - rwa.x * f0.x) * (1.0f - rwa.y * f0.y)
                  * (1.0f - rwa.z * f0.z) * (1.0f - rwa.w * f0.w)
                  * (1.0f - rwb.x * f1.x) * (1.0f - rwb.y * f1.y)
                  * (1.0f - rwb.z * f1.z) * (1.0f - rwb.w * f1.w);
        float u_ = (a + b - a * b) * ret;
        out_usage[r] = u_;
        int bin = max(0, min((int)(u_ * (float)NBINS), NBINS - 1));
        atomicAdd(&g_hist[bin], 1);
    }

    // block max -> one atomic per block
#pragma unroll
    for (int o = 16; o; o >>= 1)
        enc = max(enc, __shfl_xor_sync(0xFFFFFFFFu, enc, o));
    if (lane == 0) smax[wid] = enc;
    __syncthreads();
    if (tid == 0) {
        unsigned int mx = 0u;
#pragma unroll
        for (int j = 0; j < 8; j++) mx = max(mx, smax[j]);
        atomicMax(&g_partial_max[blockIdx.x & 1023], mx);
    }
}

// ---------------- kernel 2: global max + threshold bin ----------------
__global__ void k_thresh() {
    __shared__ unsigned int sm[1024];
    __shared__ float spre[1024];
    int t = threadIdx.x;

    sm[t] = g_partial_max[t];
    __syncthreads();
    for (int o = 512; o; o >>= 1) {
        if (t < o) sm[t] = max(sm[t], sm[t + o]);
        __syncthreads();
    }
    if (t == 0) g_m = dec_f(sm[0]);

    const float inv = 1.0f / (float)NBINS;
    const int BPT = NBINS / 1024;       // 8
    int base = t * BPT;
    int cnt[BPT];
    float local = 0.0f;
#pragma unroll
    for (int b = 0; b < BPT; b++) {
        cnt[b] = g_hist[base + b];
        if (cnt[b]) local += (float)cnt[b] * __logf((float)(base + b + 1) * inv);
    }
    spre[t] = local;
    __syncthreads();
    for (int o = 1; o < 1024; o <<= 1) {
        float v = (t >= o) ? spre[t - o] : 0.0f;
        __syncthreads();
        spre[t] += v;
        __syncthreads();
    }
    float prefix = (t == 0) ? 0.0f : spre[t - 1];
    if (prefix <= LOG_BOUND) {
        atomicMin(&g_thresh_bin, base);
    } else {
        float run = prefix;
#pragma unroll
        for (int b = 0; b < BPT; b++) {
            if (cnt[b]) run += (float)cnt[b] * __logf((float)(base + b + 1) * inv);
            if (run <= LOG_BOUND) {
                atomicMin(&g_thresh_bin, base + b);
                break;
            }
        }
    }
}

// ---------------- kernel 3: softmax denominator + gather small-usage set ----
__global__ void k_gather(const float4* __restrict__ usage4, int N4) {
    __shared__ float sh[8];
    int i = blockIdx.x * blockDim.x + threadIdx.x;
    int lane = threadIdx.x & 31;
    int wid  = threadIdx.x >> 5;
    float e = 0.0f;
    float m = g_m;
    int tb = g_thresh_bin;
    if (i < N4) {
        const float4 s4 = reinterpret_cast<const float4*>(g_s)[i];
        float4 u4 = usage4[i];
        e = expf(s4.x - m) + expf(s4.y - m) + expf(s4.z - m) + expf(s4.w - m);
        float uu[4] = {u4.x, u4.y, u4.z, u4.w};
#pragma unroll
        for (int c = 0; c < 4; c++) {
            int bin = (int)(uu[c] * (float)NBINS);
            bin = max(0, min(bin, NBINS - 1));
            if (bin <= tb) {
                int p = atomicAdd(&g_count, 1);
                if (p < K_MAX) {
                    g_buf_u[p] = uu[c];
                    g_buf_lu[p] = logf(uu[c]);
                    g_buf_idx[p] = i * 4 + c;
                }
            }
        }
    }
#pragma unroll
    for (int o = 16; o; o >>= 1) e += __shfl_xor_sync(0xFFFFFFFFu, e, o);
    if (lane == 0) sh[wid] = e;
    __syncthreads();
    if (threadIdx.x == 0) {
        float t = 0.0f;
#pragma unroll
        for (int j = 0; j < 8; j++) t += sh[j];
        atomicAdd(&g_Z, t);
    }
}

// ---------------- kernel 4: allocation for selected head (warp / element) ----
__global__ void k_alloc() {
    int C = min(g_count, K_MAX);
    int w = (blockIdx.x * blockDim.x + threadIdx.x) >> 5;
    int lane = threadIdx.x & 31;
    if (w >= C) return;
    float ui = g_buf_u[w];
    int ii = g_buf_idx[w];
    float S = 0.0f;
    for (int j = lane; j < C; j += 32) {
        float uj = g_buf_u[j];
        bool before = (uj < ui) || (uj == ui && g_buf_idx[j] < ii);
        if (before) S += g_buf_lu[j];
    }
#pragma unroll
    for (int o = 16; o; o >>= 1) S += __shfl_xor_sync(0xFFFFFFFFu, S, o);
    if (lane == 0) {
        float a = (1.0f - ui) * expf(S);
        g_buf_a[w] = a;
        atomicAdd(&g_sum_alloc, a);
    }
}

// ---------------- kernel 5: finalize content part of ww + precedence --------
__global__ void k_final(const float4* __restrict__ prec4,
                        const float* __restrict__ ag_p,
                        const float* __restrict__ wg_p,
                        float* __restrict__ out, int N, int N4) {
    int i = blockIdx.x * blockDim.x + threadIdx.x;
    if (i >= N4) return;
    float invZ = 1.0f / g_Z;
    float m = g_m;
    float ag = ag_p[0];
    float wg = wg_p[0];
    float cw = wg * (1.0f - ag);
    float sum_ww = wg * (ag * g_sum_alloc + (1.0f - ag));
    float oms = 1.0f - sum_ww;

    float4 s4 = reinterpret_cast<const float4*>(g_s)[i];
    float4 p4 = prec4[i];
    float4 ww, np;
    ww.x = cw * expf(s4.x - m) * invZ;
    ww.y = cw * expf(s4.y - m) * invZ;
    ww.z = cw * expf(s4.z - m) * invZ;
    ww.w = cw * expf(s4.w - m) * invZ;
    np.x = oms * p4.x + ww.x;
    np.y = oms * p4.y + ww.y;
    np.z = oms * p4.z + ww.z;
    np.w = oms * p4.w + ww.w;
    reinterpret_cast<float4*>(out)[i] = ww;
    reinterpret_cast<float4*>(out + 2 * N)[i] = np;
}

// ---------------- kernel 6: scatter-add allocation contributions ------------
__global__ void k_apply(const float* __restrict__ ag_p,
                        const float* __restrict__ wg_p,
                        float* __restrict__ out, int N) {
    int C = min(g_count, K_MAX);
    int w = blockIdx.x * blockDim.x + threadIdx.x;
    if (w >= C) return;
    float val = wg_p[0] * ag_p[0] * g_buf_a[w];
    int ii = g_buf_idx[w];
    out[ii] += val;          // indices unique -> no atomics needed
    out[2 * N + ii] += val;
}

// ---------------- launcher ----------------
extern "C" void kernel_launch(void* const* d_in, const int* in_sizes, int n_in,
                              void* d_out, int out_size) {
    const float* mem  = (const float*)d_in[0];
    const float* key  = (const float*)d_in[1];
    const float* beta = (const float*)d_in[2];
    const float* fg   = (const float*)d_in[3];
    const float* rw   = (const float*)d_in[4];
    const float* pu   = (const float*)d_in[5];
    const float* pw   = (const float*)d_in[6];
    const float* ag   = (const float*)d_in[7];
    const float* wg   = (const float*)d_in[8];
    const float* prec = (const float*)d_in[9];

    int N = in_sizes[0] / 64;   // W = 64
    int N4 = N / 4;

    float* out = (float*)d_out;
    float* out_usage = out + N; // outputs: [ww | usage | new_precedence]

    static int smem_set = 0;
    if (!smem_set) {
        cudaFuncSetAttribute(k_main, cudaFuncAttributeMaxDynamicSharedMemorySize,
                             (int)MAIN_SMEM);
        smem_set = 1;
    }

    k_init<<<1, 64>>>(key);                 // idx 0
    k_zero_a<<<4, 256>>>();                 // idx 1
    k_zero_b<<<NBINS / 256, 256>>>();       // idx 2
    k_main<<<(N + TILE_ROWS - 1) / TILE_ROWS, 256, MAIN_SMEM>>>(   // idx 3
        (const float4*)mem, (const float4*)key, beta, fg, (const float4*)rw,
        pu, pw, out_usage, N);
    k_thresh<<<1, 1024>>>();
    k_gather<<<(N4 + 255) / 256, 256>>>((const float4*)out_usage, N4);
    k_alloc<<<512, 1024>>>();
    k_final<<<(N4 + 255) / 256, 256>>>((const float4*)prec, ag, wg, out, N, N4);
    k_apply<<<(K_MAX + 255) / 256, 256>>>(ag, wg, out, N);
}